// round 3
// baseline (speedup 1.0000x reference)
#include <cuda_runtime.h>
#include <math.h>

#define BATCH  128
#define SEQL   512
#define EMBED  512
#define HIDDEN 1024
#define NCLS   1000

#define NCTA   128        // persistent grid size (128 <= 148 SMs, occ 1 guaranteed)
#define KSPLIT 4          // recurrent K=1024 split into 4 chunks of 256

typedef unsigned long long ull;

// ---------------- scratch (device globals: no allocation allowed) -------------
__device__ float g_X[2][SEQL][BATCH * HIDDEN];     // x_t @ W_in + b (both gates)
__device__ float g_Pz[KSPLIT][BATCH * HIDDEN];     // k-split partials, z gate
__device__ float g_Ph[KSPLIT][BATCH * HIDDEN];     // k-split partials, h gate
__device__ float g_h[2][BATCH * HIDDEN];           // ping-pong hidden state

// grid barrier: ONE monotonic counter, no resets, launch-state-invariant
__device__ unsigned g_bar_count = 0;

// ---------------- f32x2 helpers (FFMA2: 2 fp32 FMA per instruction) -----------
__device__ __forceinline__ ull pk2(float x) {
    ull r;
    unsigned int u = __float_as_uint(x);
    asm("mov.b64 %0, {%1, %1};" : "=l"(r) : "r"(u));
    return r;
}
__device__ __forceinline__ void fma2(ull& c, ull a, ull b) {
    asm("fma.rn.f32x2 %0, %1, %2, %0;" : "+l"(c) : "l"(a), "l"(b));
}
__device__ __forceinline__ float2 upk(ull c) {
    unsigned int lo, hi;
    asm("mov.b64 {%0, %1}, %2;" : "=r"(lo), "=r"(hi) : "l"(c));
    return make_float2(__uint_as_float(lo), __uint_as_float(hi));
}

// ---------------- grid-wide barrier --------------------------------------------
// Monotonic counter: each arrival's epoch target derives from its OWN add result,
// so the barrier is correct for any starting value that is a multiple of NCTA
// (true at every launch boundary: each launch adds exactly 1024*NCTA).
__device__ __forceinline__ void grid_barrier() {
    __syncthreads();
    if (threadIdx.x == 0) {
        __threadfence();                                    // release
        unsigned old = atomicAdd(&g_bar_count, 1u);
        unsigned target = old - (old % NCTA) + NCTA;        // end of my epoch
        while (*((volatile unsigned*)&g_bar_count) < target) { }
        __threadfence();                                    // acquire
    }
    __syncthreads();
}

// ---------------- init: zero h0 + reset barrier counter ------------------------
__global__ void init_kernel() {
    int i = blockIdx.x * 256 + threadIdx.x;
    g_h[0][i] = 0.0f;
    if (i == 0) g_bar_count = 0;   // hygiene; 0 is a valid (multiple-of-NCTA) start
}

// ---------------- Kernel 1: embedding gather + input projection ---------------
// C[r, n] = emb[x[r]] @ W{z,h}[0:512, :] + b{z,h}   for r in [0, 65536)
__global__ __launch_bounds__(256) void gemm_embed(
    const int*   __restrict__ x,
    const float* __restrict__ emb,
    const float* __restrict__ Wz, const float* __restrict__ bz,
    const float* __restrict__ Wh, const float* __restrict__ bh)
{
    __shared__ float As[32][65];
    __shared__ float Bs[32][64];
    __shared__ int   sidx[64];

    const int m0 = blockIdx.y * 64;
    const int n0 = blockIdx.x * 64;          // 0..2047
    const int g  = n0 >> 10;                 // gate: 0 = z, 1 = h
    const int j0 = n0 & 1023;
    const float* W    = g ? Wh : Wz;
    const float* bias = g ? bh : bz;

    const int tid = threadIdx.x;
    if (tid < 64) sidx[tid] = x[m0 + tid];
    __syncthreads();

    const int ty = tid >> 4, tx = tid & 15;

    ull acc[4][2];
#pragma unroll
    for (int i = 0; i < 4; i++) { acc[i][0] = 0ull; acc[i][1] = 0ull; }

    for (int k0 = 0; k0 < EMBED; k0 += 32) {
#pragma unroll
        for (int p = 0; p < 8; p++) {        // A tile 64x32 (k-major in smem)
            int m = (tid >> 5) + p * 8;
            int k = tid & 31;
            As[k][m] = emb[(long)sidx[m] * EMBED + k0 + k];
        }
#pragma unroll
        for (int p = 0; p < 8; p++) {        // B tile 32x64
            int k = (tid >> 6) + p * 4;
            int n = tid & 63;
            Bs[k][n] = W[(long)(k0 + k) * HIDDEN + j0 + n];
        }
        __syncthreads();
#pragma unroll
        for (int kk = 0; kk < 32; kk++) {
            ull b0 = *(const ull*)&Bs[kk][tx * 4];
            ull b1 = *(const ull*)&Bs[kk][tx * 4 + 2];
#pragma unroll
            for (int i = 0; i < 4; i++) {
                ull a = pk2(As[kk][ty * 4 + i]);
                fma2(acc[i][0], a, b0);
                fma2(acc[i][1], a, b1);
            }
        }
        __syncthreads();
    }

    float bv0 = bias[j0 + tx * 4];
    float bv1 = bias[j0 + tx * 4 + 1];
    float bv2 = bias[j0 + tx * 4 + 2];
    float bv3 = bias[j0 + tx * 4 + 3];
#pragma unroll
    for (int i = 0; i < 4; i++) {
        int r = m0 + ty * 4 + i;
        int b = r >> 9, t = r & 511;         // r = b*512 + t
        float* dst = &g_X[g][t][b * HIDDEN + j0 + tx * 4];
        float2 c0 = upk(acc[i][0]), c1 = upk(acc[i][1]);
        dst[0] = c0.x + bv0;
        dst[1] = c0.y + bv1;
        dst[2] = c1.x + bv2;
        dst[3] = c1.y + bv3;
    }
}

// ---------------- Kernel 2: persistent recurrence (all 512 steps) -------------
// 128 CTAs. CTA -> (ks, mtile, ntile). Each CTA computes partial GEMMs for BOTH
// gates of one 64x64 output tile over a 256-wide K chunk, then all CTAs barrier,
// reduce partials + apply gating, barrier, next step.
__global__ __launch_bounds__(256) void recurrent_persistent(
    const float* __restrict__ Wz,
    const float* __restrict__ Wh)
{
    const int cta   = blockIdx.x;
    const int ks    = cta & 3;           // k-split id
    const int tile  = cta >> 2;          // 0..31
    const int m0    = (tile & 1) * 64;   // 2 m-tiles
    const int n0    = (tile >> 1) * 64;  // 16 n-tiles
    const int kbase = ks * 256;

    __shared__ float As [32][68];        // row stride 272B: 16B-aligned float4 rows
    __shared__ float Bzs[32][64];
    __shared__ float Bhs[32][64];

    const int tid = threadIdx.x;
    const int ty = tid >> 4, tx = tid & 15;

    // staging-load indices
    const int lm = tid >> 5;             // + p*8   (A rows)
    const int lk = tid & 31;             // A col within k-tile
    const int bk = tid >> 6;             // + p*4   (B rows)
    const int bn = tid & 63;             // B col

    const long wrow0 = (long)(EMBED + kbase) * HIDDEN + n0 + bn;

    // update-phase element base (4 consecutive floats per thread)
    const int ubase = (cta * 256 + tid) * 4;

    for (int t = 0; t < SEQL; t++) {
        const int par = t & 1;
        const float* h_in = g_h[par];

        ull accz[4][2], acch[4][2];
#pragma unroll
        for (int i = 0; i < 4; i++) {
            accz[i][0] = 0ull; accz[i][1] = 0ull;
            acch[i][0] = 0ull; acch[i][1] = 0ull;
        }

        // prologue: stage first k-tile into registers
        float ra[8], rbz[8], rbh[8];
#pragma unroll
        for (int p = 0; p < 8; p++) {
            ra[p]  = __ldcg(&h_in[(m0 + lm + p * 8) * HIDDEN + kbase + lk]);
            rbz[p] = Wz[wrow0 + (long)(bk + p * 4) * HIDDEN];
            rbh[p] = Wh[wrow0 + (long)(bk + p * 4) * HIDDEN];
        }

        for (int k0 = 0; k0 < 256; k0 += 32) {
            __syncthreads();                 // previous compute done
#pragma unroll
            for (int p = 0; p < 8; p++) {
                As [lk][lm + p * 8]  = ra[p];
                Bzs[bk + p * 4][bn]  = rbz[p];
                Bhs[bk + p * 4][bn]  = rbh[p];
            }
            __syncthreads();

            if (k0 + 32 < 256) {             // prefetch next k-tile
#pragma unroll
                for (int p = 0; p < 8; p++) {
                    ra[p]  = __ldcg(&h_in[(m0 + lm + p * 8) * HIDDEN + kbase + k0 + 32 + lk]);
                    rbz[p] = Wz[wrow0 + (long)(k0 + 32 + bk + p * 4) * HIDDEN];
                    rbh[p] = Wh[wrow0 + (long)(k0 + 32 + bk + p * 4) * HIDDEN];
                }
            }

#pragma unroll
            for (int kk = 0; kk < 32; kk++) {
                float4 a4 = *(const float4*)&As[kk][ty * 4];
                ulonglong2 bz = *(const ulonglong2*)&Bzs[kk][tx * 4];
                ulonglong2 bh = *(const ulonglong2*)&Bhs[kk][tx * 4];
                ull a;
                a = pk2(a4.x);
                fma2(accz[0][0], a, bz.x); fma2(accz[0][1], a, bz.y);
                fma2(acch[0][0], a, bh.x); fma2(acch[0][1], a, bh.y);
                a = pk2(a4.y);
                fma2(accz[1][0], a, bz.x); fma2(accz[1][1], a, bz.y);
                fma2(acch[1][0], a, bh.x); fma2(acch[1][1], a, bh.y);
                a = pk2(a4.z);
                fma2(accz[2][0], a, bz.x); fma2(accz[2][1], a, bz.y);
                fma2(acch[2][0], a, bh.x); fma2(acch[2][1], a, bh.y);
                a = pk2(a4.w);
                fma2(accz[3][0], a, bz.x); fma2(accz[3][1], a, bz.y);
                fma2(acch[3][0], a, bh.x); fma2(acch[3][1], a, bh.y);
            }
        }

        // write partials (L1-bypass: consumed by other SMs)
#pragma unroll
        for (int i = 0; i < 4; i++) {
            int off = (m0 + ty * 4 + i) * HIDDEN + n0 + tx * 4;
            float2 c0 = upk(accz[i][0]), c1 = upk(accz[i][1]);
            __stcg((float4*)&g_Pz[ks][off], make_float4(c0.x, c0.y, c1.x, c1.y));
            float2 d0 = upk(acch[i][0]), d1 = upk(acch[i][1]);
            __stcg((float4*)&g_Ph[ks][off], make_float4(d0.x, d0.y, d1.x, d1.y));
        }

        grid_barrier();

        // ---- reduce partials + gate + state update (4 elems per thread) ----
        {
            float4 zs = *(const float4*)&g_X[0][t][ubase];
            float4 hs = *(const float4*)&g_X[1][t][ubase];
#pragma unroll
            for (int s = 0; s < KSPLIT; s++) {
                float4 pz = __ldcg((const float4*)&g_Pz[s][ubase]);
                float4 ph = __ldcg((const float4*)&g_Ph[s][ubase]);
                zs.x += pz.x; zs.y += pz.y; zs.z += pz.z; zs.w += pz.w;
                hs.x += ph.x; hs.y += ph.y; hs.z += ph.z; hs.w += ph.w;
            }
            float4 hp = __ldcg((const float4*)&g_h[par][ubase]);
            float4 hn;
            { float z = 1.0f / (1.0f + __expf(-zs.x)); hn.x = hp.x + z * (tanhf(hs.x) - hp.x); }
            { float z = 1.0f / (1.0f + __expf(-zs.y)); hn.y = hp.y + z * (tanhf(hs.y) - hp.y); }
            { float z = 1.0f / (1.0f + __expf(-zs.z)); hn.z = hp.z + z * (tanhf(hs.z) - hp.z); }
            { float z = 1.0f / (1.0f + __expf(-zs.w)); hn.w = hp.w + z * (tanhf(hs.w) - hp.w); }
            __stcg((float4*)&g_h[par ^ 1][ubase], hn);
        }

        grid_barrier();
    }
}

// ---------------- Kernel 3: final FC  logits = h @ Wfc + bfc ------------------
__global__ void fc_kernel(const float* __restrict__ Wfc,
                          const float* __restrict__ bfc,
                          float* __restrict__ out)
{
    int n = blockIdx.x * 64 + threadIdx.x;
    int b = blockIdx.y * 4 + threadIdx.y;
    if (n >= NCLS) return;
    const float* hr = &g_h[0][b * HIDDEN];    // final state (t=511 writes parity 0)
    float acc = 0.0f;
#pragma unroll 8
    for (int k = 0; k < HIDDEN; k++)
        acc += hr[k] * __ldg(&Wfc[k * NCLS + n]);
    out[b * NCLS + n] = acc + bfc[n];
}

// ---------------- launch (4 graph nodes total) ---------------------------------
extern "C" void kernel_launch(void* const* d_in, const int* in_sizes, int n_in,
                              void* d_out, int out_size)
{
    const int*   x   = (const int*)d_in[0];
    const float* emb = (const float*)d_in[1];
    const float* Wz  = (const float*)d_in[2];
    const float* bz  = (const float*)d_in[3];
    const float* Wh  = (const float*)d_in[4];
    const float* bh  = (const float*)d_in[5];
    const float* Wfc = (const float*)d_in[6];
    const float* bfc = (const float*)d_in[7];
    float* out = (float*)d_out;

    init_kernel<<<512, 256>>>();
    gemm_embed<<<dim3(32, 1024), 256>>>(x, emb, Wz, bz, Wh, bh);
    recurrent_persistent<<<NCTA, 256>>>(Wz, Wh);
    fc_kernel<<<dim3(16, 32), dim3(64, 4)>>>(Wfc, bfc, out);
}

// round 5
// speedup vs baseline: 1.3345x; 1.3345x over previous
#include <cuda_runtime.h>
#include <cuda_bf16.h>
#include <math.h>
#include <stdint.h>

#define BATCH  128
#define SEQL   512
#define EMBED  512
#define HIDDEN 1024
#define NCLS   1000
#define NTOT   2048          // both gates side by side (z: 0..1023, h~: 1024..2047)

#define NCTA   128
#define KSPLIT 4             // K=1024 split into 4 chunks of 256

typedef unsigned long long ull;
typedef unsigned int u32;

// ---------------- device scratch (no allocation allowed) ----------------------
__device__ float g_X[2][SEQL][BATCH * HIDDEN];   // x_t @ W_in + b, per gate
__device__ float g_P[KSPLIT][BATCH * NTOT];      // k-split partials, both gates
__device__ float g_h[2][BATCH * HIDDEN];         // fp32 hidden state ping-pong
__device__ __nv_bfloat16 g_hhi[BATCH * HIDDEN];  // bf16 split of current h
__device__ __nv_bfloat16 g_hlo[BATCH * HIDDEN];
__device__ __nv_bfloat16 g_Wt_hi[NTOT * HIDDEN]; // recurrent weights, transposed [n][k]
__device__ __nv_bfloat16 g_Wt_lo[NTOT * HIDDEN];

// flag barrier state (reset by init_kernel each launch/replay)
__device__ unsigned g_flags[NCTA];
__device__ unsigned g_release;

// ---------------- f32x2 helpers (embed kernel) --------------------------------
__device__ __forceinline__ ull pk2(float x) {
    ull r; u32 u = __float_as_uint(x);
    asm("mov.b64 %0, {%1, %1};" : "=l"(r) : "r"(u));
    return r;
}
__device__ __forceinline__ void fma2(ull& c, ull a, ull b) {
    asm("fma.rn.f32x2 %0, %1, %2, %0;" : "+l"(c) : "l"(a), "l"(b));
}
__device__ __forceinline__ float2 upk(ull c) {
    u32 lo, hi;
    asm("mov.b64 {%0, %1}, %2;" : "=r"(lo), "=r"(hi) : "l"(c));
    return make_float2(__uint_as_float(lo), __uint_as_float(hi));
}

// ---------------- warp MMA helpers (arch-generic: sm_80+) ---------------------
__device__ __forceinline__ u32 smem_u32(const void* p) {
    u32 a;
    asm("{ .reg .u64 t; cvta.to.shared.u64 t, %1; cvt.u32.u64 %0, t; }" : "=r"(a) : "l"(p));
    return a;
}
__device__ __forceinline__ void ldmx4(u32* r, u32 addr) {
    asm volatile("ldmatrix.sync.aligned.m8n8.x4.shared.b16 {%0,%1,%2,%3}, [%4];"
                 : "=r"(r[0]), "=r"(r[1]), "=r"(r[2]), "=r"(r[3]) : "r"(addr));
}
__device__ __forceinline__ void mma16816(float* c, const u32* a, u32 b0, u32 b1) {
    asm volatile("mma.sync.aligned.m16n8k16.row.col.f32.bf16.bf16.f32 "
                 "{%0,%1,%2,%3}, {%4,%5,%6,%7}, {%8,%9}, {%0,%1,%2,%3};"
                 : "+f"(c[0]), "+f"(c[1]), "+f"(c[2]), "+f"(c[3])
                 : "r"(a[0]), "r"(a[1]), "r"(a[2]), "r"(a[3]), "r"(b0), "r"(b1));
}

// SMEM layout for the persistent kernel (padded rows: 264 bf16 = 528 B, 16B-aligned,
// odd 16B-chunk stride -> conflict-free ldmatrix)
#define STRE 264
#define STRB (STRE * 2)
#define OFF_AHI 0
#define OFF_ALO (OFF_AHI + 128 * STRB)      // 67584
#define OFF_BHI (OFF_ALO + 128 * STRB)      // 135168
#define OFF_BLO (OFF_BHI + 64 * STRB)       // 168960
#define SMEM_PERSIST (OFF_BLO + 64 * STRB)  // 202752

// ---------------- grid barrier (flag slots + master + release word) -----------
__device__ __forceinline__ void grid_barrier(int cta, unsigned gen) {
    __syncthreads();
    if (threadIdx.x == 0) {
        __threadfence();
        *((volatile unsigned*)&g_flags[cta]) = gen;
    }
    if (cta == 0) {
        if (threadIdx.x < NCTA) {
            while (*((volatile unsigned*)&g_flags[threadIdx.x]) != gen) { }
        }
        __syncthreads();
        if (threadIdx.x == 0) {
            __threadfence();
            *((volatile unsigned*)&g_release) = gen;
        }
    }
    if (threadIdx.x == 0) {
        while (*((volatile unsigned*)&g_release) != gen) { }
        __threadfence();
    }
    __syncthreads();
}

// ---------------- init: zero h0 / bf16 h / barrier state ----------------------
__global__ void init_kernel() {
    int i = blockIdx.x * 256 + threadIdx.x;          // 0..131071
    g_h[0][i] = 0.0f;
    g_hhi[i] = __float2bfloat16(0.0f);
    g_hlo[i] = __float2bfloat16(0.0f);
    if (i < NCTA) g_flags[i] = 0;
    if (i == 0) g_release = 0;
}

// ---------------- weight prep: transpose + bf16 hi/lo split -------------------
// Wt[n][k] = (n<1024 ? Wz : Wh)[(512+k)*HIDDEN + (n&1023)]
__global__ void prep_weights(const float* __restrict__ Wz,
                             const float* __restrict__ Wh)
{
    __shared__ float tile[32][33];
    const int k0  = blockIdx.x * 32;
    const int n0g = blockIdx.y * 32;
    const float* W = (n0g < 1024) ? Wz : Wh;
    const int nc0 = n0g & 1023;

    for (int r = threadIdx.y; r < 32; r += 8)
        tile[r][threadIdx.x] = W[(long)(512 + k0 + r) * HIDDEN + nc0 + threadIdx.x];
    __syncthreads();

    for (int r2 = threadIdx.y; r2 < 32; r2 += 8) {
        float v = tile[threadIdx.x][r2];
        __nv_bfloat16 hi = __float2bfloat16_rn(v);
        __nv_bfloat16 lo = __float2bfloat16_rn(v - __bfloat162float(hi));
        long o = (long)(n0g + r2) * HIDDEN + k0 + threadIdx.x;
        g_Wt_hi[o] = hi;
        g_Wt_lo[o] = lo;
    }
}

// ---------------- Kernel 1: embedding gather + input projection (SIMT) --------
__global__ __launch_bounds__(256) void gemm_embed(
    const int*   __restrict__ x,
    const float* __restrict__ emb,
    const float* __restrict__ Wz, const float* __restrict__ bz,
    const float* __restrict__ Wh, const float* __restrict__ bh)
{
    __shared__ float As[32][65];
    __shared__ float Bs[32][64];
    __shared__ int   sidx[64];

    const int m0 = blockIdx.y * 64;
    const int n0 = blockIdx.x * 64;
    const int g  = n0 >> 10;
    const int j0 = n0 & 1023;
    const float* W    = g ? Wh : Wz;
    const float* bias = g ? bh : bz;

    const int tid = threadIdx.x;
    if (tid < 64) sidx[tid] = x[m0 + tid];
    __syncthreads();

    const int ty = tid >> 4, tx = tid & 15;

    ull acc[4][2];
#pragma unroll
    for (int i = 0; i < 4; i++) { acc[i][0] = 0ull; acc[i][1] = 0ull; }

    for (int k0 = 0; k0 < EMBED; k0 += 32) {
#pragma unroll
        for (int p = 0; p < 8; p++) {
            int m = (tid >> 5) + p * 8;
            int k = tid & 31;
            As[k][m] = emb[(long)sidx[m] * EMBED + k0 + k];
        }
#pragma unroll
        for (int p = 0; p < 8; p++) {
            int k = (tid >> 6) + p * 4;
            int n = tid & 63;
            Bs[k][n] = W[(long)(k0 + k) * HIDDEN + j0 + n];
        }
        __syncthreads();
#pragma unroll
        for (int kk = 0; kk < 32; kk++) {
            ull b0 = *(const ull*)&Bs[kk][tx * 4];
            ull b1 = *(const ull*)&Bs[kk][tx * 4 + 2];
#pragma unroll
            for (int i = 0; i < 4; i++) {
                ull a = pk2(As[kk][ty * 4 + i]);
                fma2(acc[i][0], a, b0);
                fma2(acc[i][1], a, b1);
            }
        }
        __syncthreads();
    }

    float bv0 = bias[j0 + tx * 4];
    float bv1 = bias[j0 + tx * 4 + 1];
    float bv2 = bias[j0 + tx * 4 + 2];
    float bv3 = bias[j0 + tx * 4 + 3];
#pragma unroll
    for (int i = 0; i < 4; i++) {
        int r = m0 + ty * 4 + i;
        int b = r >> 9, t = r & 511;
        float* dst = &g_X[g][t][b * HIDDEN + j0 + tx * 4];
        float2 c0 = upk(acc[i][0]), c1 = upk(acc[i][1]);
        dst[0] = c0.x + bv0;
        dst[1] = c0.y + bv1;
        dst[2] = c1.x + bv2;
        dst[3] = c1.y + bv3;
    }
}

// ---------------- Kernel 2: persistent HMMA recurrence ------------------------
// 128 CTAs: cta -> (ks = cta&3 : K chunk of 256, nt = cta>>2 : 64-col tile of NTOT).
// B (weights, bf16 hi/lo, [n][k]) resident in SMEM for all 512 steps.
// Per step: stage A = h_hi/h_lo chunk to SMEM; 8 warps compute the 128x64 C tile
// via mma.sync bf16 (3 split products); partials -> g_P; barrier; reduce + gate;
// barrier.
__global__ __launch_bounds__(256, 1) void recurrent_persistent()
{
    extern __shared__ char smem[];
    const u32 sbase = smem_u32(smem);
    const int tid  = threadIdx.x;
    const int wid  = tid >> 5, lane = tid & 31;
    const int cta  = blockIdx.x;
    const int ks   = cta & 3;
    const int n0   = (cta >> 2) * 64;
    const int kbase = ks * 256;

    // ---- load resident B tiles: 64 rows x 256 k, hi+lo ----
#pragma unroll
    for (int it = 0; it < 8; it++) {
        int idx = tid + it * 256;            // 0..2047 (uint4 = 8 bf16 each)
        int row = idx >> 5;                  // 0..63
        int c   = idx & 31;
        long src = (long)(n0 + row) * HIDDEN + kbase + c * 8;
        *(uint4*)(smem + OFF_BHI + row * STRB + c * 16) = *(const uint4*)&g_Wt_hi[src];
        *(uint4*)(smem + OFF_BLO + row * STRB + c * 16) = *(const uint4*)&g_Wt_lo[src];
    }

    // warp tiling: 4 (m) x 2 (n) warps, each owns 32x32 of the 128x64 C tile
    const int wm = wid & 3, wn = wid >> 2;
    const int m_base = wm * 32, n_base = wn * 32;
    const int grp = lane >> 2, tg = lane & 3;

    // ldmatrix lane->address components
    const u32 a_row = (u32)(lane & 15);          // A: rows m0-15, k half by lane>>4
    const u32 a_kof = (u32)((lane >> 4) * 8);
    const u32 b_row = (u32)((((lane >> 3) & 1) * 8) + (lane & 7));  // B: n quadrants
    const u32 b_kof = (u32)((lane >> 4) * 8);

    const u32 aHi0 = sbase + OFF_AHI + (m_base + a_row) * STRB + a_kof * 2;
    const u32 aLo0 = sbase + OFF_ALO + (m_base + a_row) * STRB + a_kof * 2;
    const u32 bHi0 = sbase + OFF_BHI + (n_base + b_row) * STRB + b_kof * 2;
    const u32 bLo0 = sbase + OFF_BLO + (n_base + b_row) * STRB + b_kof * 2;

    // reduce-phase assignment: 4 consecutive h elements per thread
    const int ubase = (cta * 256 + tid) * 4;
    const int um = ubase >> 10;
    const int uj = ubase & 1023;

    unsigned gen = 0;

    for (int t = 0; t < SEQL; t++) {
        const int par = t & 1;

        __syncthreads();   // B staged (t==0) / previous step fully done
        // ---- stage A tiles (h_hi / h_lo): 128 rows x 256 k ----
#pragma unroll
        for (int it = 0; it < 16; it++) {
            int idx = tid + it * 256;        // 0..4095
            int row = idx >> 5;              // 0..127
            int c   = idx & 31;
            long src = (long)row * HIDDEN + kbase + c * 8;
            *(uint4*)(smem + OFF_AHI + row * STRB + c * 16) = __ldcg((const uint4*)&g_hhi[src]);
            *(uint4*)(smem + OFF_ALO + row * STRB + c * 16) = __ldcg((const uint4*)&g_hlo[src]);
        }
        __syncthreads();

        // ---- HMMA mainloop: 16 k16-steps x 3 split products ----
        float c[2][4][4];
#pragma unroll
        for (int mi = 0; mi < 2; mi++)
#pragma unroll
            for (int nf = 0; nf < 4; nf++)
#pragma unroll
                for (int r = 0; r < 4; r++) c[mi][nf][r] = 0.0f;

#pragma unroll 4
        for (int k16 = 0; k16 < 16; k16++) {
            const u32 kb = (u32)(k16 * 32);  // 16 bf16 = 32 bytes
            u32 ah[2][4], al[2][4], bhv[2][4], blv[2][4];
#pragma unroll
            for (int mi = 0; mi < 2; mi++) {
                ldmx4(ah[mi], aHi0 + mi * 16 * STRB + kb);
                ldmx4(al[mi], aLo0 + mi * 16 * STRB + kb);
            }
#pragma unroll
            for (int nb = 0; nb < 2; nb++) {
                ldmx4(bhv[nb], bHi0 + nb * 16 * STRB + kb);
                ldmx4(blv[nb], bLo0 + nb * 16 * STRB + kb);
            }
#pragma unroll
            for (int mi = 0; mi < 2; mi++) {
#pragma unroll
                for (int nf = 0; nf < 4; nf++) {
                    int nb = nf >> 1, hf = nf & 1;
                    mma16816(c[mi][nf], ah[mi], bhv[nb][hf], bhv[nb][2 + hf]);
                    mma16816(c[mi][nf], ah[mi], blv[nb][hf], blv[nb][2 + hf]);
                    mma16816(c[mi][nf], al[mi], bhv[nb][hf], bhv[nb][2 + hf]);
                }
            }
        }

        // ---- epilogue: C -> g_P partials (L1-bypass) ----
#pragma unroll
        for (int mi = 0; mi < 2; mi++) {
#pragma unroll
            for (int nf = 0; nf < 4; nf++) {
                int row = m_base + mi * 16 + grp;
                int col = n0 + n_base + nf * 8 + tg * 2;
                __stcg((float2*)&g_P[ks][row * NTOT + col],
                       make_float2(c[mi][nf][0], c[mi][nf][1]));
                __stcg((float2*)&g_P[ks][(row + 8) * NTOT + col],
                       make_float2(c[mi][nf][2], c[mi][nf][3]));
            }
        }

        grid_barrier(cta, ++gen);

        // ---- reduce partials + gate + state update ----
        {
            float4 zs = *(const float4*)&g_X[0][t][um * HIDDEN + uj];
            float4 hs = *(const float4*)&g_X[1][t][um * HIDDEN + uj];
#pragma unroll
            for (int s = 0; s < KSPLIT; s++) {
                float4 pz = __ldcg((const float4*)&g_P[s][um * NTOT + uj]);
                float4 ph = __ldcg((const float4*)&g_P[s][um * NTOT + 1024 + uj]);
                zs.x += pz.x; zs.y += pz.y; zs.z += pz.z; zs.w += pz.w;
                hs.x += ph.x; hs.y += ph.y; hs.z += ph.z; hs.w += ph.w;
            }
            float4 hp = __ldcg((const float4*)&g_h[par][um * HIDDEN + uj]);
            float4 hn;
            { float z = 1.0f / (1.0f + __expf(-zs.x)); hn.x = hp.x + z * (tanhf(hs.x) - hp.x); }
            { float z = 1.0f / (1.0f + __expf(-zs.y)); hn.y = hp.y + z * (tanhf(hs.y) - hp.y); }
            { float z = 1.0f / (1.0f + __expf(-zs.z)); hn.z = hp.z + z * (tanhf(hs.z) - hp.z); }
            { float z = 1.0f / (1.0f + __expf(-zs.w)); hn.w = hp.w + z * (tanhf(hs.w) - hp.w); }
            __stcg((float4*)&g_h[par ^ 1][um * HIDDEN + uj], hn);

            float v[4] = {hn.x, hn.y, hn.z, hn.w};
            unsigned short hiu[4], lou[4];
#pragma unroll
            for (int i = 0; i < 4; i++) {
                __nv_bfloat16 hb = __float2bfloat16_rn(v[i]);
                __nv_bfloat16 lb = __float2bfloat16_rn(v[i] - __bfloat162float(hb));
                hiu[i] = __bfloat16_as_ushort(hb);
                lou[i] = __bfloat16_as_ushort(lb);
            }
            ull hpack = (ull)hiu[0] | ((ull)hiu[1] << 16) | ((ull)hiu[2] << 32) | ((ull)hiu[3] << 48);
            ull lpack = (ull)lou[0] | ((ull)lou[1] << 16) | ((ull)lou[2] << 32) | ((ull)lou[3] << 48);
            __stcg((ull*)&g_hhi[um * HIDDEN + uj], hpack);
            __stcg((ull*)&g_hlo[um * HIDDEN + uj], lpack);
        }

        grid_barrier(cta, ++gen);
    }
}

// ---------------- Kernel 3: final FC  logits = h @ Wfc + bfc ------------------
__global__ __launch_bounds__(128) void fc_kernel(
    const float* __restrict__ Wfc,
    const float* __restrict__ bfc,
    float* __restrict__ out)
{
    extern __shared__ float hsm[];                // [16][1024]
    const int b0 = blockIdx.y * 16;
    const int tid = threadIdx.x;

    for (int i = tid; i < 16 * HIDDEN / 4; i += 128)
        ((float4*)hsm)[i] = *(const float4*)&g_h[0][b0 * HIDDEN + i * 4];
    __syncthreads();

    const int n = blockIdx.x * 128 + tid;
    if (n >= NCLS) return;

    float acc[16];
#pragma unroll
    for (int i = 0; i < 16; i++) acc[i] = 0.0f;

    for (int k = 0; k < HIDDEN; k += 4) {
        float w0 = Wfc[(long)(k + 0) * NCLS + n];
        float w1 = Wfc[(long)(k + 1) * NCLS + n];
        float w2 = Wfc[(long)(k + 2) * NCLS + n];
        float w3 = Wfc[(long)(k + 3) * NCLS + n];
#pragma unroll
        for (int i = 0; i < 16; i++) {
            float4 h4 = *(const float4*)&hsm[i * HIDDEN + k];
            acc[i] += w0 * h4.x + w1 * h4.y + w2 * h4.z + w3 * h4.w;
        }
    }
    float bv = bfc[n];
#pragma unroll
    for (int i = 0; i < 16; i++)
        out[(long)(b0 + i) * NCLS + n] = acc[i] + bv;
}

// ---------------- launch (5 graph nodes) ---------------------------------------
extern "C" void kernel_launch(void* const* d_in, const int* in_sizes, int n_in,
                              void* d_out, int out_size)
{
    const int*   x   = (const int*)d_in[0];
    const float* emb = (const float*)d_in[1];
    const float* Wz  = (const float*)d_in[2];
    const float* bz  = (const float*)d_in[3];
    const float* Wh  = (const float*)d_in[4];
    const float* bh  = (const float*)d_in[5];
    const float* Wfc = (const float*)d_in[6];
    const float* bfc = (const float*)d_in[7];
    float* out = (float*)d_out;

    cudaFuncSetAttribute(recurrent_persistent,
                         cudaFuncAttributeMaxDynamicSharedMemorySize, SMEM_PERSIST);
    cudaFuncSetAttribute(fc_kernel,
                         cudaFuncAttributeMaxDynamicSharedMemorySize, 16 * HIDDEN * 4);

    init_kernel<<<512, 256>>>();
    prep_weights<<<dim3(32, 64), dim3(32, 8)>>>(Wz, Wh);
    gemm_embed<<<dim3(32, 1024), 256>>>(x, emb, Wz, bz, Wh, bh);
    recurrent_persistent<<<NCTA, 256, SMEM_PERSIST>>>();
    fc_kernel<<<dim3(8, 8), 128, 16 * HIDDEN * 4>>>(Wfc, bfc, out);
}

// round 6
// speedup vs baseline: 1.7698x; 1.3262x over previous
#include <cuda_runtime.h>
#include <cuda_bf16.h>
#include <math.h>
#include <stdint.h>

#define BATCH  128
#define SEQL   512
#define EMBED  512
#define HIDDEN 1024
#define NCLS   1000
#define NTOT   2048

#define NCTA   128
#define KSPLIT 4

typedef unsigned long long ull;
typedef unsigned int u32;

// ---------------- device scratch -----------------------------------------------
__device__ float g_X[2][SEQL][BATCH * HIDDEN];     // x_t @ W_in + b, per gate
__device__ float g_P[KSPLIT][BATCH * NTOT];        // k-split partials
__device__ __nv_bfloat16 g_hhi[2][BATCH * HIDDEN]; // h state, bf16 hi (ping-pong)
__device__ __nv_bfloat16 g_hlo[2][BATCH * HIDDEN]; // h state, bf16 lo
__device__ __nv_bfloat16 g_Wt_hi[NTOT * HIDDEN];   // recurrent W^T hi  [n][k]
__device__ __nv_bfloat16 g_Wt_lo[NTOT * HIDDEN];
__device__ __nv_bfloat16 g_Win_hi[NTOT * EMBED];   // input-proj W^T hi [n][k]
__device__ __nv_bfloat16 g_Win_lo[NTOT * EMBED];
__device__ __nv_bfloat16 g_emb_hi[32000 * EMBED];  // emb table bf16 hi
__device__ __nv_bfloat16 g_emb_lo[32000 * EMBED];

__device__ unsigned g_flags[NCTA];
__device__ unsigned g_release;

// ---------------- MMA / ldmatrix / cp.async helpers ----------------------------
__device__ __forceinline__ u32 smem_u32(const void* p) {
    u32 a;
    asm("{ .reg .u64 t; cvta.to.shared.u64 t, %1; cvt.u32.u64 %0, t; }" : "=r"(a) : "l"(p));
    return a;
}
__device__ __forceinline__ void ldmx4(u32* r, u32 addr) {
    asm volatile("ldmatrix.sync.aligned.m8n8.x4.shared.b16 {%0,%1,%2,%3}, [%4];"
                 : "=r"(r[0]), "=r"(r[1]), "=r"(r[2]), "=r"(r[3]) : "r"(addr));
}
__device__ __forceinline__ void mma16816(float* c, const u32* a, u32 b0, u32 b1) {
    asm volatile("mma.sync.aligned.m16n8k16.row.col.f32.bf16.bf16.f32 "
                 "{%0,%1,%2,%3}, {%4,%5,%6,%7}, {%8,%9}, {%0,%1,%2,%3};"
                 : "+f"(c[0]), "+f"(c[1]), "+f"(c[2]), "+f"(c[3])
                 : "r"(a[0]), "r"(a[1]), "r"(a[2]), "r"(a[3]), "r"(b0), "r"(b1));
}
#define CP16(dst, src) \
    asm volatile("cp.async.cg.shared.global [%0], [%1], 16;" :: "r"(dst), "l"(src) : "memory")
#define CP_COMMIT() asm volatile("cp.async.commit_group;" ::: "memory")
#define CP_WAIT1()  asm volatile("cp.async.wait_group 1;" ::: "memory")
#define CP_WAIT0()  asm volatile("cp.async.wait_group 0;" ::: "memory")

// ---------------- grid barrier --------------------------------------------------
__device__ __forceinline__ void grid_barrier(int cta, unsigned gen) {
    __syncthreads();
    if (threadIdx.x == 0) {
        __threadfence();
        *((volatile unsigned*)&g_flags[cta]) = gen;
    }
    if (cta == 0) {
        if (threadIdx.x < NCTA) {
            while (*((volatile unsigned*)&g_flags[threadIdx.x]) != gen) { }
        }
        __syncthreads();
        if (threadIdx.x == 0) {
            __threadfence();
            *((volatile unsigned*)&g_release) = gen;
        }
    }
    if (threadIdx.x == 0) {
        while (*((volatile unsigned*)&g_release) != gen) { }
        __threadfence();
    }
    __syncthreads();
}

// ---------------- init ----------------------------------------------------------
__global__ void init_kernel() {
    int i = blockIdx.x * 256 + threadIdx.x;           // 0..131071
    __nv_bfloat16 z = __float2bfloat16(0.0f);
    g_hhi[0][i] = z; g_hhi[1][i] = z;
    g_hlo[0][i] = z; g_hlo[1][i] = z;
    if (i < NCTA) g_flags[i] = 0;
    if (i == 0) g_release = 0;
}

// ---------------- emb table -> bf16 hi/lo --------------------------------------
__global__ void conv_emb(const float* __restrict__ emb) {
    long i = (long)blockIdx.x * 256 + threadIdx.x;    // one float4 each; 4,096,000 total
    float4 v = *(const float4*)&emb[i * 4];
    float f[4] = {v.x, v.y, v.z, v.w};
    unsigned short hiu[4], lou[4];
#pragma unroll
    for (int j = 0; j < 4; j++) {
        __nv_bfloat16 hb = __float2bfloat16_rn(f[j]);
        __nv_bfloat16 lb = __float2bfloat16_rn(f[j] - __bfloat162float(hb));
        hiu[j] = __bfloat16_as_ushort(hb);
        lou[j] = __bfloat16_as_ushort(lb);
    }
    *(ull*)&g_emb_hi[i * 4] = (ull)hiu[0] | ((ull)hiu[1] << 16) | ((ull)hiu[2] << 32) | ((ull)hiu[3] << 48);
    *(ull*)&g_emb_lo[i * 4] = (ull)lou[0] | ((ull)lou[1] << 16) | ((ull)lou[2] << 32) | ((ull)lou[3] << 48);
}

// ---------------- weight prep: recurrent part (k in [512,1536)) -----------------
__global__ void prep_weights(const float* __restrict__ Wz,
                             const float* __restrict__ Wh)
{
    __shared__ float tile[32][33];
    const int k0  = blockIdx.x * 32;
    const int n0g = blockIdx.y * 32;
    const float* W = (n0g < 1024) ? Wz : Wh;
    const int nc0 = n0g & 1023;

    for (int r = threadIdx.y; r < 32; r += 8)
        tile[r][threadIdx.x] = W[(long)(512 + k0 + r) * HIDDEN + nc0 + threadIdx.x];
    __syncthreads();
    for (int r2 = threadIdx.y; r2 < 32; r2 += 8) {
        float v = tile[threadIdx.x][r2];
        __nv_bfloat16 hi = __float2bfloat16_rn(v);
        __nv_bfloat16 lo = __float2bfloat16_rn(v - __bfloat162float(hi));
        long o = (long)(n0g + r2) * HIDDEN + k0 + threadIdx.x;
        g_Wt_hi[o] = hi;
        g_Wt_lo[o] = lo;
    }
}

// ---------------- weight prep: input part (k in [0,512)) ------------------------
__global__ void prep_win(const float* __restrict__ Wz,
                         const float* __restrict__ Wh)
{
    __shared__ float tile[32][33];
    const int k0  = blockIdx.x * 32;     // < 512
    const int n0g = blockIdx.y * 32;     // < 2048
    const float* W = (n0g < 1024) ? Wz : Wh;
    const int nc0 = n0g & 1023;

    for (int r = threadIdx.y; r < 32; r += 8)
        tile[r][threadIdx.x] = W[(long)(k0 + r) * HIDDEN + nc0 + threadIdx.x];
    __syncthreads();
    for (int r2 = threadIdx.y; r2 < 32; r2 += 8) {
        float v = tile[threadIdx.x][r2];
        __nv_bfloat16 hi = __float2bfloat16_rn(v);
        __nv_bfloat16 lo = __float2bfloat16_rn(v - __bfloat162float(hi));
        long o = (long)(n0g + r2) * EMBED + k0 + threadIdx.x;
        g_Win_hi[o] = hi;
        g_Win_lo[o] = lo;
    }
}

// ---------------- Kernel 1: HMMA embedding projection --------------------------
// C tile 128(M) x 128(N), K=512 in 8 tiles of 64, cp.async double-buffered.
// SMEM per buffer: A_hi, A_lo, B_hi, B_lo each 128 rows x 144B = 18432 B.
#define E_STRB 144
#define E_MAT  18432
#define E_BUF  (4 * E_MAT)           // 73728
#define E_SIDX (2 * E_BUF)           // 147456
#define SMEM_EMBED (E_SIDX + 512)

__global__ __launch_bounds__(256, 1) void gemm_embed_mma(
    const int*   __restrict__ x,
    const float* __restrict__ bz,
    const float* __restrict__ bh)
{
    extern __shared__ char smem[];
    const u32 sbase = smem_u32(smem);
    const int tid = threadIdx.x;
    const int wid = tid >> 5, lane = tid & 31;
    const int n0 = blockIdx.x * 128;          // 0..2047 (one gate per CTA)
    const int m0 = blockIdx.y * 128;

    int* sidx = (int*)(smem + E_SIDX);
    if (tid < 128) sidx[tid] = x[m0 + tid];
    __syncthreads();

    // staging indices: 4 uint4 per thread per matrix
    const int srow[4] = { (tid + 0)   >> 3, (tid + 256) >> 3,
                          (tid + 512) >> 3, (tid + 768) >> 3 };
    const int sc = tid & 7;

    // issue one 64-k tile (A hi/lo + B hi/lo) into buffer b
    auto issue_tile = [&](int kt, int b) {
        const int k0 = kt * 64;
#pragma unroll
        for (int j = 0; j < 4; j++) {
            int row = srow[j];
            u32 dst = sbase + b * E_BUF + row * E_STRB + sc * 16;
            long aoff = (long)sidx[row] * EMBED + k0 + sc * 8;
            long boff = (long)(n0 + row) * EMBED + k0 + sc * 8;
            CP16(dst,             (const void*)&g_emb_hi[aoff]);
            CP16(dst + E_MAT,     (const void*)&g_emb_lo[aoff]);
            CP16(dst + 2 * E_MAT, (const void*)&g_Win_hi[boff]);
            CP16(dst + 3 * E_MAT, (const void*)&g_Win_lo[boff]);
        }
        CP_COMMIT();
    };

    // warp tiling: 4(m) x 2(n) warps; warp tile 32 x 64
    const int m_base = (wid & 3) * 32;
    const int n_base = (wid >> 2) * 64;
    const u32 a_row = (u32)(lane & 15);
    const u32 b_row = (u32)((((lane >> 3) & 1) * 8) + (lane & 7));
    const u32 khalf = (u32)((lane >> 4) * 16);   // byte offset for k-half

    float c[2][8][4];
#pragma unroll
    for (int mi = 0; mi < 2; mi++)
#pragma unroll
        for (int nf = 0; nf < 8; nf++)
#pragma unroll
            for (int r = 0; r < 4; r++) c[mi][nf][r] = 0.0f;

    issue_tile(0, 0);

    for (int kt = 0; kt < 8; kt++) {
        if (kt < 7) { issue_tile(kt + 1, (kt + 1) & 1); CP_WAIT1(); }
        else        { CP_WAIT0(); }
        __syncthreads();

        const u32 base = sbase + (kt & 1) * E_BUF;
#pragma unroll
        for (int k16 = 0; k16 < 4; k16++) {
            const u32 kb = (u32)(k16 * 32) + khalf;
            u32 ah[2][4], al[2][4], bhv[4][4], blv[4][4];
#pragma unroll
            for (int mi = 0; mi < 2; mi++) {
                u32 ar = base + (m_base + mi * 16 + a_row) * E_STRB + kb;
                ldmx4(ah[mi], ar);
                ldmx4(al[mi], ar + E_MAT);
            }
#pragma unroll
            for (int nb = 0; nb < 4; nb++) {
                u32 br = base + 2 * E_MAT + (n_base + nb * 16 + b_row) * E_STRB + kb;
                ldmx4(bhv[nb], br);
                ldmx4(blv[nb], br + E_MAT);
            }
#pragma unroll
            for (int mi = 0; mi < 2; mi++) {
#pragma unroll
                for (int nf = 0; nf < 8; nf++) {
                    int nb = nf >> 1, hf = nf & 1;
                    mma16816(c[mi][nf], ah[mi], bhv[nb][hf], bhv[nb][2 + hf]);
                    mma16816(c[mi][nf], ah[mi], blv[nb][hf], blv[nb][2 + hf]);
                    mma16816(c[mi][nf], al[mi], bhv[nb][hf], bhv[nb][2 + hf]);
                }
            }
        }
        __syncthreads();
    }

    // epilogue: scatter into g_X with bias
    const int g  = n0 >> 10;
    const int j0 = n0 & 1023;
    const float* bias = g ? bh : bz;
    const int grp = lane >> 2, tg = lane & 3;

#pragma unroll
    for (int nf = 0; nf < 8; nf++) {
        int col = j0 + n_base + nf * 8 + tg * 2;
        float bv0 = bias[col], bv1 = bias[col + 1];
#pragma unroll
        for (int mi = 0; mi < 2; mi++) {
            int r0 = m0 + m_base + mi * 16 + grp;
            int b0i = r0 >> 9, t0 = r0 & 511;
            *(float2*)&g_X[g][t0][b0i * HIDDEN + col] =
                make_float2(c[mi][nf][0] + bv0, c[mi][nf][1] + bv1);
            int r1 = r0 + 8;
            int b1i = r1 >> 9, t1 = r1 & 511;
            *(float2*)&g_X[g][t1][b1i * HIDDEN + col] =
                make_float2(c[mi][nf][2] + bv0, c[mi][nf][3] + bv1);
        }
    }
}

// ---------------- Kernel 2: persistent HMMA recurrence -------------------------
#define STRE 264
#define STRB (STRE * 2)
#define OFF_AHI 0
#define OFF_ALO (OFF_AHI + 128 * STRB)
#define OFF_BHI (OFF_ALO + 128 * STRB)
#define OFF_BLO (OFF_BHI + 64 * STRB)
#define SMEM_PERSIST (OFF_BLO + 64 * STRB)

__global__ __launch_bounds__(256, 1) void recurrent_persistent()
{
    extern __shared__ char smem[];
    const u32 sbase = smem_u32(smem);
    const int tid  = threadIdx.x;
    const int wid  = tid >> 5, lane = tid & 31;
    const int cta  = blockIdx.x;
    const int ks   = cta & 3;
    const int n0   = (cta >> 2) * 64;
    const int kbase = ks * 256;

    // resident B tiles (weights)
#pragma unroll
    for (int it = 0; it < 8; it++) {
        int idx = tid + it * 256;
        int row = idx >> 5;
        int c   = idx & 31;
        long src = (long)(n0 + row) * HIDDEN + kbase + c * 8;
        *(uint4*)(smem + OFF_BHI + row * STRB + c * 16) = *(const uint4*)&g_Wt_hi[src];
        *(uint4*)(smem + OFF_BLO + row * STRB + c * 16) = *(const uint4*)&g_Wt_lo[src];
    }

    const int wm = wid & 3, wn = wid >> 2;
    const int m_base = wm * 32, n_base = wn * 32;
    const int grp = lane >> 2, tg = lane & 3;

    const u32 a_row = (u32)(lane & 15);
    const u32 b_row = (u32)((((lane >> 3) & 1) * 8) + (lane & 7));
    const u32 khalf = (u32)((lane >> 4) * 16);

    const u32 aHi0 = sbase + OFF_AHI + (m_base + a_row) * STRB + khalf;
    const u32 aLo0 = sbase + OFF_ALO + (m_base + a_row) * STRB + khalf;
    const u32 bHi0 = sbase + OFF_BHI + (n_base + b_row) * STRB + khalf;
    const u32 bLo0 = sbase + OFF_BLO + (n_base + b_row) * STRB + khalf;

    const int ubase = (cta * 256 + tid) * 4;
    const int um = ubase >> 10;
    const int uj = ubase & 1023;

    unsigned gen = 0;

    for (int t = 0; t < SEQL; t++) {
        const int par = t & 1;
        const __nv_bfloat16* hhi = g_hhi[par];
        const __nv_bfloat16* hlo = g_hlo[par];

        __syncthreads();
        // stage A tiles (h hi/lo)
#pragma unroll
        for (int it = 0; it < 16; it++) {
            int idx = tid + it * 256;
            int row = idx >> 5;
            int c   = idx & 31;
            long src = (long)row * HIDDEN + kbase + c * 8;
            *(uint4*)(smem + OFF_AHI + row * STRB + c * 16) = __ldcg((const uint4*)&hhi[src]);
            *(uint4*)(smem + OFF_ALO + row * STRB + c * 16) = __ldcg((const uint4*)&hlo[src]);
        }
        __syncthreads();

        // prefetch this step's input-projection values (DRAM) for the reduce phase
        float4 zs = *(const float4*)&g_X[0][t][um * HIDDEN + uj];
        float4 hs = *(const float4*)&g_X[1][t][um * HIDDEN + uj];

        // HMMA mainloop
        float c[2][4][4];
#pragma unroll
        for (int mi = 0; mi < 2; mi++)
#pragma unroll
            for (int nf = 0; nf < 4; nf++)
#pragma unroll
                for (int r = 0; r < 4; r++) c[mi][nf][r] = 0.0f;

#pragma unroll 4
        for (int k16 = 0; k16 < 16; k16++) {
            const u32 kb = (u32)(k16 * 32);
            u32 ah[2][4], al[2][4], bhv[2][4], blv[2][4];
#pragma unroll
            for (int mi = 0; mi < 2; mi++) {
                ldmx4(ah[mi], aHi0 + mi * 16 * STRB + kb);
                ldmx4(al[mi], aLo0 + mi * 16 * STRB + kb);
            }
#pragma unroll
            for (int nb = 0; nb < 2; nb++) {
                ldmx4(bhv[nb], bHi0 + nb * 16 * STRB + kb);
                ldmx4(blv[nb], bLo0 + nb * 16 * STRB + kb);
            }
#pragma unroll
            for (int mi = 0; mi < 2; mi++) {
#pragma unroll
                for (int nf = 0; nf < 4; nf++) {
                    int nb = nf >> 1, hf = nf & 1;
                    mma16816(c[mi][nf], ah[mi], bhv[nb][hf], bhv[nb][2 + hf]);
                    mma16816(c[mi][nf], ah[mi], blv[nb][hf], blv[nb][2 + hf]);
                    mma16816(c[mi][nf], al[mi], bhv[nb][hf], bhv[nb][2 + hf]);
                }
            }
        }

        // epilogue: partials -> g_P
#pragma unroll
        for (int mi = 0; mi < 2; mi++) {
#pragma unroll
            for (int nf = 0; nf < 4; nf++) {
                int row = m_base + mi * 16 + grp;
                int col = n0 + n_base + nf * 8 + tg * 2;
                __stcg((float2*)&g_P[ks][row * NTOT + col],
                       make_float2(c[mi][nf][0], c[mi][nf][1]));
                __stcg((float2*)&g_P[ks][(row + 8) * NTOT + col],
                       make_float2(c[mi][nf][2], c[mi][nf][3]));
            }
        }

        grid_barrier(cta, ++gen);

        // reduce + gate + update
        {
#pragma unroll
            for (int s = 0; s < KSPLIT; s++) {
                float4 pz = __ldcg((const float4*)&g_P[s][um * NTOT + uj]);
                float4 ph = __ldcg((const float4*)&g_P[s][um * NTOT + 1024 + uj]);
                zs.x += pz.x; zs.y += pz.y; zs.z += pz.z; zs.w += pz.w;
                hs.x += ph.x; hs.y += ph.y; hs.z += ph.z; hs.w += ph.w;
            }
            // previous h from hi/lo
            ull hp_hi = __ldcg((const ull*)&g_hhi[par][um * HIDDEN + uj]);
            ull hp_lo = __ldcg((const ull*)&g_hlo[par][um * HIDDEN + uj]);
            float hpf[4];
#pragma unroll
            for (int i = 0; i < 4; i++) {
                __nv_bfloat16 a = __ushort_as_bfloat16((unsigned short)(hp_hi >> (16 * i)));
                __nv_bfloat16 b = __ushort_as_bfloat16((unsigned short)(hp_lo >> (16 * i)));
                hpf[i] = __bfloat162float(a) + __bfloat162float(b);
            }
            float zv[4] = {zs.x, zs.y, zs.z, zs.w};
            float hv[4] = {hs.x, hs.y, hs.z, hs.w};
            unsigned short hiu[4], lou[4];
#pragma unroll
            for (int i = 0; i < 4; i++) {
                float z  = 1.0f / (1.0f + __expf(-zv[i]));
                float hn = hpf[i] + z * (tanhf(hv[i]) - hpf[i]);
                __nv_bfloat16 hb = __float2bfloat16_rn(hn);
                __nv_bfloat16 lb = __float2bfloat16_rn(hn - __bfloat162float(hb));
                hiu[i] = __bfloat16_as_ushort(hb);
                lou[i] = __bfloat16_as_ushort(lb);
            }
            ull hpack = (ull)hiu[0] | ((ull)hiu[1] << 16) | ((ull)hiu[2] << 32) | ((ull)hiu[3] << 48);
            ull lpack = (ull)lou[0] | ((ull)lou[1] << 16) | ((ull)lou[2] << 32) | ((ull)lou[3] << 48);
            __stcg((ull*)&g_hhi[par ^ 1][um * HIDDEN + uj], hpack);
            __stcg((ull*)&g_hlo[par ^ 1][um * HIDDEN + uj], lpack);
        }

        grid_barrier(cta, ++gen);
    }
}

// ---------------- Kernel 3: final FC --------------------------------------------
__global__ __launch_bounds__(128) void fc_kernel(
    const float* __restrict__ Wfc,
    const float* __restrict__ bfc,
    float* __restrict__ out)
{
    extern __shared__ float hsm[];                // [16][1024]
    const int b0 = blockIdx.y * 16;
    const int tid = threadIdx.x;

    for (int i = tid; i < 16 * HIDDEN / 4; i += 128) {
        ull hi4 = *(const ull*)&g_hhi[0][b0 * HIDDEN + i * 4];
        ull lo4 = *(const ull*)&g_hlo[0][b0 * HIDDEN + i * 4];
        float4 v;
        float* vp = (float*)&v;
#pragma unroll
        for (int j = 0; j < 4; j++) {
            __nv_bfloat16 a = __ushort_as_bfloat16((unsigned short)(hi4 >> (16 * j)));
            __nv_bfloat16 b = __ushort_as_bfloat16((unsigned short)(lo4 >> (16 * j)));
            vp[j] = __bfloat162float(a) + __bfloat162float(b);
        }
        ((float4*)hsm)[i] = v;
    }
    __syncthreads();

    const int n = blockIdx.x * 128 + tid;
    if (n >= NCLS) return;

    float acc[16];
#pragma unroll
    for (int i = 0; i < 16; i++) acc[i] = 0.0f;

    for (int k = 0; k < HIDDEN; k += 4) {
        float w0 = Wfc[(long)(k + 0) * NCLS + n];
        float w1 = Wfc[(long)(k + 1) * NCLS + n];
        float w2 = Wfc[(long)(k + 2) * NCLS + n];
        float w3 = Wfc[(long)(k + 3) * NCLS + n];
#pragma unroll
        for (int i = 0; i < 16; i++) {
            float4 h4 = *(const float4*)&hsm[i * HIDDEN + k];
            acc[i] += w0 * h4.x + w1 * h4.y + w2 * h4.z + w3 * h4.w;
        }
    }
    float bv = bfc[n];
#pragma unroll
    for (int i = 0; i < 16; i++)
        out[(long)(b0 + i) * NCLS + n] = acc[i] + bv;
}

// ---------------- launch ---------------------------------------------------------
extern "C" void kernel_launch(void* const* d_in, const int* in_sizes, int n_in,
                              void* d_out, int out_size)
{
    const int*   x   = (const int*)d_in[0];
    const float* emb = (const float*)d_in[1];
    const float* Wz  = (const float*)d_in[2];
    const float* bz  = (const float*)d_in[3];
    const float* Wh  = (const float*)d_in[4];
    const float* bh  = (const float*)d_in[5];
    const float* Wfc = (const float*)d_in[6];
    const float* bfc = (const float*)d_in[7];
    float* out = (float*)d_out;

    cudaFuncSetAttribute(gemm_embed_mma,
                         cudaFuncAttributeMaxDynamicSharedMemorySize, SMEM_EMBED);
    cudaFuncSetAttribute(recurrent_persistent,
                         cudaFuncAttributeMaxDynamicSharedMemorySize, SMEM_PERSIST);
    cudaFuncSetAttribute(fc_kernel,
                         cudaFuncAttributeMaxDynamicSharedMemorySize, 16 * HIDDEN * 4);

    init_kernel<<<512, 256>>>();
    conv_emb<<<16000, 256>>>(emb);
    prep_weights<<<dim3(32, 64), dim3(32, 8)>>>(Wz, Wh);
    prep_win<<<dim3(16, 64), dim3(32, 8)>>>(Wz, Wh);
    gemm_embed_mma<<<dim3(16, 512), 256, SMEM_EMBED>>>(x, bz, bh);
    recurrent_persistent<<<NCTA, 256, SMEM_PERSIST>>>();
    fc_kernel<<<dim3(8, 8), 128, 16 * HIDDEN * 4>>>(Wfc, bfc, out);
}